// round 2
// baseline (speedup 1.0000x reference)
#include <cuda_runtime.h>

#define BB 8
#define CC 64
#define NN 400
#define NN2 (NN * NN)          // 160000
#define NV4 (NN / 4)           // 100 float4 per row
#define KT 32                  // k-tile width in kernel 3

// Scratch (device globals: no allocation allowed in kernel_launch)
__device__ float g_At[BB * NN2];       // At[b][n][k] = A[b,k,n] = relu(tanh(max_c R[b,c,k,n]))
__device__ float g_x[BB * CC * NN];    // x[b][c][k]

// ---------------------------------------------------------------------------
// Kernel 1: channel max + relu(tanh), written TRANSPOSED.
// Block (32,8) computes a 32x32 tile of the (i,j) plane: m[i,j] = max_c R[b,c,i,j],
// f = relu(tanh(m)), writes g_At[b][j][i] via smem tile transpose.
// Reads coalesced in j (fast index of R); writes coalesced in i.
// Streams all of R (327 MB) -> DRAM-bound, same structure that hit 80.6% SOL.
// ---------------------------------------------------------------------------
__global__ void k1_maxtanh_T(const float* __restrict__ R) {
    __shared__ float t[32][33];
    const int b  = blockIdx.z;
    const int i0 = blockIdx.y * 32;
    const int j0 = blockIdx.x * 32;
    const int x  = threadIdx.x;               // j lane
    const int y  = threadIdx.y;               // 0..7

    // Clamp indices so every lane issues full-warp loads to valid memory;
    // results for clamped (duplicate) positions are simply not written.
    const int j  = j0 + x;
    const int jc = (j < NN) ? j : (NN - 1);

    int ic[4];
    #pragma unroll
    for (int q = 0; q < 4; ++q) {
        int i = i0 + y + 8 * q;
        ic[q] = (i < NN) ? i : (NN - 1);
    }

    const float* base = R + (size_t)b * CC * NN2 + jc;
    size_t roff[4];
    #pragma unroll
    for (int q = 0; q < 4; ++q) roff[q] = (size_t)ic[q] * NN;

    float m0 = -3.4e38f, m1 = -3.4e38f, m2 = -3.4e38f, m3 = -3.4e38f;
    #pragma unroll 2
    for (int c = 0; c < CC; c += 2) {
        const float* p0 = base + (size_t)c * NN2;
        const float* p1 = base + (size_t)(c + 1) * NN2;
        float v00 = p0[roff[0]], v01 = p0[roff[1]], v02 = p0[roff[2]], v03 = p0[roff[3]];
        float v10 = p1[roff[0]], v11 = p1[roff[1]], v12 = p1[roff[2]], v13 = p1[roff[3]];
        m0 = fmaxf(m0, fmaxf(v00, v10));
        m1 = fmaxf(m1, fmaxf(v01, v11));
        m2 = fmaxf(m2, fmaxf(v02, v12));
        m3 = fmaxf(m3, fmaxf(v03, v13));
    }

    // f = relu(tanh(m)); store into smem at [j_local][i_local]
    t[x][y +  0] = (m0 > 0.f) ? tanhf(m0) : 0.f;
    t[x][y +  8] = (m1 > 0.f) ? tanhf(m1) : 0.f;
    t[x][y + 16] = (m2 > 0.f) ? tanhf(m2) : 0.f;
    t[x][y + 24] = (m3 > 0.f) ? tanhf(m3) : 0.f;
    __syncthreads();

    // Write At[b][j][i]: row j (slow), i fast -> coalesced in x
    const int iw = i0 + x;
    if (iw < NN) {
        #pragma unroll
        for (int q = 0; q < 4; ++q) {
            int jw = j0 + y + 8 * q;
            if (jw < NN)
                g_At[((size_t)b * NN + jw) * NN + iw] = t[y + 8 * q][x];
        }
    }
}

// ---------------------------------------------------------------------------
// Kernel 2: x[b,c,k] = sum_n R[b,c,n,k] * At[b,n,k]   (pure aligned streams)
// Block (32,8): warp y -> channel c = cg*8 + y; lane x -> float4 slot k4.
// All 8 warps read the SAME At line per n -> L1 reuse; R is the only DRAM stream.
// No shared memory, float4 LDG only, 2 accumulator chains.
// ---------------------------------------------------------------------------
__global__ void k2_gather(const float* __restrict__ R) {
    const int b  = blockIdx.z;
    const int cg = blockIdx.y;                // 0..7
    const int kt = blockIdx.x;                // 0..3
    const int x  = threadIdx.x;
    const int y  = threadIdx.y;
    const int c  = cg * 8 + y;
    const int k4 = kt * 32 + x;               // float4 index
    if (k4 >= NV4) return;                    // only tile 3 diverges

    const float4* Rv = reinterpret_cast<const float4*>(
                           R + (size_t)(b * CC + c) * NN2) + k4;
    const float4* Av = reinterpret_cast<const float4*>(
                           g_At + (size_t)b * NN2) + k4;

    float4 s0 = make_float4(0.f, 0.f, 0.f, 0.f);
    float4 s1 = make_float4(0.f, 0.f, 0.f, 0.f);
    #pragma unroll 4
    for (int n = 0; n < NN; n += 2) {
        float4 a0 = Av[(size_t)n * NV4];
        float4 r0 = Rv[(size_t)n * NV4];
        float4 a1 = Av[(size_t)(n + 1) * NV4];
        float4 r1 = Rv[(size_t)(n + 1) * NV4];
        s0.x = fmaf(r0.x, a0.x, s0.x); s0.y = fmaf(r0.y, a0.y, s0.y);
        s0.z = fmaf(r0.z, a0.z, s0.z); s0.w = fmaf(r0.w, a0.w, s0.w);
        s1.x = fmaf(r1.x, a1.x, s1.x); s1.y = fmaf(r1.y, a1.y, s1.y);
        s1.z = fmaf(r1.z, a1.z, s1.z); s1.w = fmaf(r1.w, a1.w, s1.w);
    }
    float4 out;
    out.x = s0.x + s1.x; out.y = s0.y + s1.y;
    out.z = s0.z + s1.z; out.w = s0.w + s1.w;
    reinterpret_cast<float4*>(g_x + (size_t)(b * CC + c) * NN)[k4] = out;
}

// ---------------------------------------------------------------------------
// Kernel 3: out[b,o,k] = sum_c W[o,c] * x[b,c,k] + bias[o]   (tiny epilogue)
// ---------------------------------------------------------------------------
__global__ void k3_linear(const float* __restrict__ W,
                          const float* __restrict__ bias,
                          float* __restrict__ out) {
    __shared__ float xs[CC][KT + 1];
    const int b  = blockIdx.z;
    const int k0 = blockIdx.x * KT;
    const int x  = threadIdx.x;
    const int y  = threadIdx.y;
    const int k  = k0 + x;
    const bool valid = (k < NN);

    for (int c = y; c < CC; c += 8)
        xs[c][x] = valid ? g_x[((size_t)b * CC + c) * NN + k] : 0.f;
    __syncthreads();

    for (int o = y; o < CC; o += 8) {
        float acc = bias[o];
        const float* wr = W + o * CC;
        #pragma unroll 16
        for (int c = 0; c < CC; ++c)
            acc = fmaf(wr[c], xs[c][x], acc);
        if (valid)
            out[((size_t)b * CC + o) * NN + k] = acc;
    }
}

// ---------------------------------------------------------------------------
extern "C" void kernel_launch(void* const* d_in, const int* in_sizes, int n_in,
                              void* d_out, int out_size) {
    const float* R    = (const float*)d_in[0];
    const float* W    = (const float*)d_in[1];
    const float* bias = (const float*)d_in[2];
    float*       out  = (float*)d_out;

    // Kernel 1: (13 x 13 x 8) = 1352 blocks of 256 threads
    {
        dim3 grid((NN + 31) / 32, (NN + 31) / 32, BB);
        dim3 blk(32, 8);
        k1_maxtanh_T<<<grid, blk>>>(R);
    }

    // Kernel 2: (4 k-tiles x 8 c-groups x 8 b) = 256 blocks, no smem
    {
        dim3 grid((NV4 + 31) / 32, 8, BB);
        dim3 blk(32, 8);
        k2_gather<<<grid, blk>>>(R);
    }

    // Kernel 3: tiny epilogue (104 blocks)
    {
        dim3 grid((NN + KT - 1) / KT, 1, BB);
        dim3 blk(32, 8);
        k3_linear<<<grid, blk>>>(W, bias, out);
    }
}

// round 3
// speedup vs baseline: 1.6363x; 1.6363x over previous
#include <cuda_runtime.h>

#define BB 8
#define CC 64
#define NN 400
#define NN2 (NN * NN)          // 160000
#define NV4 (NN / 4)           // 100 float4 per row
#define NS 8                   // n-split chunks in kernel 2
#define NCHUNK (NN / NS)       // 50
#define KT 32                  // k-tile width in kernel 3

// Scratch (device globals: no allocation allowed in kernel_launch)
__device__ float g_A [BB * NN2];            // A[b][k][n]               (5.12 MB)
__device__ float g_At[BB * NN2];            // At[b][n][k] = A[b][k][n] (5.12 MB)
__device__ float g_xp[NS * BB * CC * NN];   // partial x sums           (6.55 MB)

// ---------------------------------------------------------------------------
// Kernel 1 (verbatim from R1: measured 80.6% DRAM SOL, 52.3us):
// channel max + relu(tanh) -> g_A. One float4 per thread, 64 c-planes.
// ---------------------------------------------------------------------------
__global__ void k1_maxtanh(const float* __restrict__ R) {
    const int per_b = NN2 / 4;                         // 40000 float4 per batch
    int t = blockIdx.x * blockDim.x + threadIdx.x;
    if (t >= BB * per_b) return;
    int b  = t / per_b;
    int i4 = (t - b * per_b) * 4;

    const float4* base =
        reinterpret_cast<const float4*>(R + (size_t)b * CC * NN2 + i4);
    const size_t plane4 = NN2 / 4;

    float4 m0 = base[0];
    float4 m1 = base[plane4];
    float4 m2 = base[2 * plane4];
    float4 m3 = base[3 * plane4];
    #pragma unroll 4
    for (int c = 4; c < CC; c += 4) {
        float4 v0 = base[(size_t)(c + 0) * plane4];
        float4 v1 = base[(size_t)(c + 1) * plane4];
        float4 v2 = base[(size_t)(c + 2) * plane4];
        float4 v3 = base[(size_t)(c + 3) * plane4];
        m0.x = fmaxf(m0.x, v0.x); m0.y = fmaxf(m0.y, v0.y); m0.z = fmaxf(m0.z, v0.z); m0.w = fmaxf(m0.w, v0.w);
        m1.x = fmaxf(m1.x, v1.x); m1.y = fmaxf(m1.y, v1.y); m1.z = fmaxf(m1.z, v1.z); m1.w = fmaxf(m1.w, v1.w);
        m2.x = fmaxf(m2.x, v2.x); m2.y = fmaxf(m2.y, v2.y); m2.z = fmaxf(m2.z, v2.z); m2.w = fmaxf(m2.w, v2.w);
        m3.x = fmaxf(m3.x, v3.x); m3.y = fmaxf(m3.y, v3.y); m3.z = fmaxf(m3.z, v3.z); m3.w = fmaxf(m3.w, v3.w);
    }
    float4 m;
    m.x = fmaxf(fmaxf(m0.x, m1.x), fmaxf(m2.x, m3.x));
    m.y = fmaxf(fmaxf(m0.y, m1.y), fmaxf(m2.y, m3.y));
    m.z = fmaxf(fmaxf(m0.z, m1.z), fmaxf(m2.z, m3.z));
    m.w = fmaxf(fmaxf(m0.w, m1.w), fmaxf(m2.w, m3.w));

    float4 a;
    a.x = (m.x > 0.f) ? tanhf(m.x) : 0.f;
    a.y = (m.y > 0.f) ? tanhf(m.y) : 0.f;
    a.z = (m.z > 0.f) ? tanhf(m.z) : 0.f;
    a.w = (m.w > 0.f) ? tanhf(m.w) : 0.f;

    reinterpret_cast<float4*>(g_A + (size_t)b * NN2 + i4)[0] = a;
}

// ---------------------------------------------------------------------------
// Kernel T: At[b][n][k] = A[b][k][n]. 32x32 smem tile transpose, 10MB traffic.
// ---------------------------------------------------------------------------
__global__ void kT_transpose() {
    __shared__ float t[32][33];
    const int b  = blockIdx.z;
    const int k0 = blockIdx.y * 32;           // rows of A
    const int n0 = blockIdx.x * 32;           // cols of A
    const int x  = threadIdx.x;
    const int y  = threadIdx.y;

    const float* Ab = g_A + (size_t)b * NN2;
    #pragma unroll
    for (int q = 0; q < 4; ++q) {
        int k = k0 + y + 8 * q;
        int n = n0 + x;
        if (k < NN && n < NN)
            t[y + 8 * q][x] = Ab[(size_t)k * NN + n];
    }
    __syncthreads();

    float* Atb = g_At + (size_t)b * NN2;
    #pragma unroll
    for (int q = 0; q < 4; ++q) {
        int n = n0 + y + 8 * q;
        int k = k0 + x;
        if (n < NN && k < NN)
            Atb[(size_t)n * NN + k] = t[x][y + 8 * q];
    }
}

// ---------------------------------------------------------------------------
// Kernel 2: partial gather, n split into NS chunks for occupancy.
//   xp[s][b][c][k] = sum_{n in chunk s} R[b,c,n,k] * At[b,n,k]
// Block (32,8): warp y -> channel c = cg*8+y; lane x -> float4 slot k4.
// Grid (4 kt, 8 cg, BB*NS) = 2048 blocks, 409K threads. Pure float4 streams,
// all warps of a block share the same At line per n (L1 reuse).
// ---------------------------------------------------------------------------
__global__ void k2_gather(const float* __restrict__ R) {
    const int bz = blockIdx.z;
    const int b  = bz / NS;
    const int ns = bz - b * NS;
    const int cg = blockIdx.y;
    const int kt = blockIdx.x;
    const int x  = threadIdx.x;
    const int y  = threadIdx.y;
    const int c  = cg * 8 + y;
    const int k4 = kt * 32 + x;
    if (k4 >= NV4) return;                    // only tile 3 partially idle

    const int n0 = ns * NCHUNK;
    const float4* Rv = reinterpret_cast<const float4*>(
                           R + (size_t)(b * CC + c) * NN2) + (size_t)n0 * NV4 + k4;
    const float4* Av = reinterpret_cast<const float4*>(
                           g_At + (size_t)b * NN2) + (size_t)n0 * NV4 + k4;

    float4 s0 = make_float4(0.f, 0.f, 0.f, 0.f);
    float4 s1 = make_float4(0.f, 0.f, 0.f, 0.f);
    #pragma unroll 5
    for (int n = 0; n < NCHUNK; n += 2) {
        float4 a0 = Av[(size_t)n * NV4];
        float4 r0 = Rv[(size_t)n * NV4];
        float4 a1 = Av[(size_t)(n + 1) * NV4];
        float4 r1 = Rv[(size_t)(n + 1) * NV4];
        s0.x = fmaf(r0.x, a0.x, s0.x); s0.y = fmaf(r0.y, a0.y, s0.y);
        s0.z = fmaf(r0.z, a0.z, s0.z); s0.w = fmaf(r0.w, a0.w, s0.w);
        s1.x = fmaf(r1.x, a1.x, s1.x); s1.y = fmaf(r1.y, a1.y, s1.y);
        s1.z = fmaf(r1.z, a1.z, s1.z); s1.w = fmaf(r1.w, a1.w, s1.w);
    }
    float4 o;
    o.x = s0.x + s1.x; o.y = s0.y + s1.y;
    o.z = s0.z + s1.z; o.w = s0.w + s1.w;
    reinterpret_cast<float4*>(g_xp)[(((size_t)ns * BB + b) * CC + c) * NV4 + k4] = o;
}

// ---------------------------------------------------------------------------
// Kernel 3: reduce NS partials + linear:
//   out[b,o,k] = sum_c W[o,c] * (sum_s xp[s][b][c][k]) + bias[o]
// ---------------------------------------------------------------------------
__global__ void k3_linear(const float* __restrict__ W,
                          const float* __restrict__ bias,
                          float* __restrict__ out) {
    __shared__ float xs[CC][KT + 1];
    const int b  = blockIdx.z;
    const int k0 = blockIdx.x * KT;
    const int x  = threadIdx.x;
    const int y  = threadIdx.y;
    const int k  = k0 + x;
    const bool valid = (k < NN);
    const int kc = valid ? k : (NN - 1);      // clamp; clamped lanes not written

    for (int c = y; c < CC; c += 8) {
        float s = 0.f;
        #pragma unroll
        for (int ssi = 0; ssi < NS; ++ssi)
            s += g_xp[(((size_t)ssi * BB + b) * CC + c) * NN + kc];
        xs[c][x] = s;
    }
    __syncthreads();

    for (int o = y; o < CC; o += 8) {
        float acc = bias[o];
        const float* wr = W + o * CC;
        #pragma unroll 16
        for (int c = 0; c < CC; ++c)
            acc = fmaf(wr[c], xs[c][x], acc);
        if (valid)
            out[((size_t)b * CC + o) * NN + k] = acc;
    }
}

// ---------------------------------------------------------------------------
extern "C" void kernel_launch(void* const* d_in, const int* in_sizes, int n_in,
                              void* d_out, int out_size) {
    const float* R    = (const float*)d_in[0];
    const float* W    = (const float*)d_in[1];
    const float* bias = (const float*)d_in[2];
    float*       out  = (float*)d_out;

    // Kernel 1: 1250 blocks x 256 (proven 80.6% DRAM SOL)
    {
        int total = BB * (NN2 / 4);
        k1_maxtanh<<<(total + 255) / 256, 256>>>(R);
    }

    // Transpose A -> At: (13 x 13 x 8) tiles
    {
        dim3 grid((NN + 31) / 32, (NN + 31) / 32, BB);
        dim3 blk(32, 8);
        kT_transpose<<<grid, blk>>>();
    }

    // Kernel 2: (4 x 8 x 64) = 2048 blocks
    {
        dim3 grid((NV4 + 31) / 32, 8, BB * NS);
        dim3 blk(32, 8);
        k2_gather<<<grid, blk>>>(R);
    }

    // Kernel 3: 104 blocks
    {
        dim3 grid((NN + KT - 1) / KT, 1, BB);
        dim3 blk(32, 8);
        k3_linear<<<grid, blk>>>(W, bias, out);
    }
}

// round 4
// speedup vs baseline: 1.6871x; 1.0311x over previous
#include <cuda_runtime.h>

#define BB 8
#define CC 64
#define NN 400
#define NN2 (NN * NN)          // 160000
#define NV4 (NN / 4)           // 100 float4 per row
#define NS 8                   // n-split chunks in kernel 2
#define NCHUNK (NN / NS)       // 50
#define KT 32                  // k-tile width in epilogue

// Scratch (device globals: no allocation allowed in kernel_launch)
__device__ float g_A [BB * NN2];            // A[b][k][n]               (5.12 MB)
__device__ float g_At[BB * NN2];            // At[b][n][k] = A[b][k][n] (5.12 MB)
__device__ float g_xp[NS * BB * CC * NN];   // partial x sums           (6.55 MB)
__device__ float g_x [BB * CC * NN];        // reduced x                (0.82 MB)

// ---------------------------------------------------------------------------
// Kernel 1 (measured 80.6% DRAM SOL, 52.3us): channel max + relu(tanh) -> g_A.
// ---------------------------------------------------------------------------
__global__ void k1_maxtanh(const float* __restrict__ R) {
    const int per_b = NN2 / 4;                         // 40000 float4 per batch
    int t = blockIdx.x * blockDim.x + threadIdx.x;
    if (t >= BB * per_b) return;
    int b  = t / per_b;
    int i4 = (t - b * per_b) * 4;

    const float4* base =
        reinterpret_cast<const float4*>(R + (size_t)b * CC * NN2 + i4);
    const size_t plane4 = NN2 / 4;

    float4 m0 = base[0];
    float4 m1 = base[plane4];
    float4 m2 = base[2 * plane4];
    float4 m3 = base[3 * plane4];
    #pragma unroll 4
    for (int c = 4; c < CC; c += 4) {
        float4 v0 = base[(size_t)(c + 0) * plane4];
        float4 v1 = base[(size_t)(c + 1) * plane4];
        float4 v2 = base[(size_t)(c + 2) * plane4];
        float4 v3 = base[(size_t)(c + 3) * plane4];
        m0.x = fmaxf(m0.x, v0.x); m0.y = fmaxf(m0.y, v0.y); m0.z = fmaxf(m0.z, v0.z); m0.w = fmaxf(m0.w, v0.w);
        m1.x = fmaxf(m1.x, v1.x); m1.y = fmaxf(m1.y, v1.y); m1.z = fmaxf(m1.z, v1.z); m1.w = fmaxf(m1.w, v1.w);
        m2.x = fmaxf(m2.x, v2.x); m2.y = fmaxf(m2.y, v2.y); m2.z = fmaxf(m2.z, v2.z); m2.w = fmaxf(m2.w, v2.w);
        m3.x = fmaxf(m3.x, v3.x); m3.y = fmaxf(m3.y, v3.y); m3.z = fmaxf(m3.z, v3.z); m3.w = fmaxf(m3.w, v3.w);
    }
    float4 m;
    m.x = fmaxf(fmaxf(m0.x, m1.x), fmaxf(m2.x, m3.x));
    m.y = fmaxf(fmaxf(m0.y, m1.y), fmaxf(m2.y, m3.y));
    m.z = fmaxf(fmaxf(m0.z, m1.z), fmaxf(m2.z, m3.z));
    m.w = fmaxf(fmaxf(m0.w, m1.w), fmaxf(m2.w, m3.w));

    float4 a;
    a.x = (m.x > 0.f) ? tanhf(m.x) : 0.f;
    a.y = (m.y > 0.f) ? tanhf(m.y) : 0.f;
    a.z = (m.z > 0.f) ? tanhf(m.z) : 0.f;
    a.w = (m.w > 0.f) ? tanhf(m.w) : 0.f;

    reinterpret_cast<float4*>(g_A + (size_t)b * NN2 + i4)[0] = a;
}

// ---------------------------------------------------------------------------
// Kernel T: At[b][n][k] = A[b][k][n]. 32x32 smem tile transpose, ~10MB traffic.
// ---------------------------------------------------------------------------
__global__ void kT_transpose() {
    __shared__ float t[32][33];
    const int b  = blockIdx.z;
    const int k0 = blockIdx.y * 32;
    const int n0 = blockIdx.x * 32;
    const int x  = threadIdx.x;
    const int y  = threadIdx.y;

    const float* Ab = g_A + (size_t)b * NN2;
    #pragma unroll
    for (int q = 0; q < 4; ++q) {
        int k = k0 + y + 8 * q;
        int n = n0 + x;
        if (k < NN && n < NN)
            t[y + 8 * q][x] = Ab[(size_t)k * NN + n];
    }
    __syncthreads();

    float* Atb = g_At + (size_t)b * NN2;
    #pragma unroll
    for (int q = 0; q < 4; ++q) {
        int n = n0 + y + 8 * q;
        int k = k0 + x;
        if (n < NN && k < NN)
            Atb[(size_t)n * NN + k] = t[x][y + 8 * q];
    }
}

// ---------------------------------------------------------------------------
// Kernel 2: partial gather, n split into NS chunks.
//   xp[s][b][c][k] = sum_{n in chunk s} R[b,c,n,k] * At[b,n,k]
// Grid (4 kt, 8 cg, BB*NS) = 2048 blocks; pure float4 streams; all 8 warps of
// a block share the same At line per n (L1 reuse).
// ---------------------------------------------------------------------------
__global__ void k2_gather(const float* __restrict__ R) {
    const int bz = blockIdx.z;
    const int b  = bz / NS;
    const int ns = bz - b * NS;
    const int cg = blockIdx.y;
    const int kt = blockIdx.x;
    const int x  = threadIdx.x;
    const int y  = threadIdx.y;
    const int c  = cg * 8 + y;
    const int k4 = kt * 32 + x;
    if (k4 >= NV4) return;

    const int n0 = ns * NCHUNK;
    const float4* Rv = reinterpret_cast<const float4*>(
                           R + (size_t)(b * CC + c) * NN2) + (size_t)n0 * NV4 + k4;
    const float4* Av = reinterpret_cast<const float4*>(
                           g_At + (size_t)b * NN2) + (size_t)n0 * NV4 + k4;

    float4 s0 = make_float4(0.f, 0.f, 0.f, 0.f);
    float4 s1 = make_float4(0.f, 0.f, 0.f, 0.f);
    #pragma unroll 5
    for (int n = 0; n < NCHUNK; n += 2) {
        float4 a0 = Av[(size_t)n * NV4];
        float4 r0 = Rv[(size_t)n * NV4];
        float4 a1 = Av[(size_t)(n + 1) * NV4];
        float4 r1 = Rv[(size_t)(n + 1) * NV4];
        s0.x = fmaf(r0.x, a0.x, s0.x); s0.y = fmaf(r0.y, a0.y, s0.y);
        s0.z = fmaf(r0.z, a0.z, s0.z); s0.w = fmaf(r0.w, a0.w, s0.w);
        s1.x = fmaf(r1.x, a1.x, s1.x); s1.y = fmaf(r1.y, a1.y, s1.y);
        s1.z = fmaf(r1.z, a1.z, s1.z); s1.w = fmaf(r1.w, a1.w, s1.w);
    }
    float4 o;
    o.x = s0.x + s1.x; o.y = s0.y + s1.y;
    o.z = s0.z + s1.z; o.w = s0.w + s1.w;
    reinterpret_cast<float4*>(g_xp)[(((size_t)ns * BB + b) * CC + c) * NV4 + k4] = o;
}

// ---------------------------------------------------------------------------
// Kernel 3a: g_x = sum_s g_xp[s]  — flat float4 elementwise reduce.
// 51200 float4 -> 200 blocks x 256. Coalesced; ~30MB traffic -> ~4.5us.
// ---------------------------------------------------------------------------
__global__ void k3a_reduce() {
    const int total4 = BB * CC * NV4;                  // 51200
    int t = blockIdx.x * blockDim.x + threadIdx.x;
    if (t >= total4) return;
    const float4* xp4 = reinterpret_cast<const float4*>(g_xp);
    const int stride4 = BB * CC * NV4;                 // float4 stride per chunk

    float4 s = xp4[t];
    #pragma unroll
    for (int ssi = 1; ssi < NS; ++ssi) {
        float4 v = xp4[(size_t)ssi * stride4 + t];
        s.x += v.x; s.y += v.y; s.z += v.z; s.w += v.w;
    }
    reinterpret_cast<float4*>(g_x)[t] = s;
}

// ---------------------------------------------------------------------------
// Kernel 3b: out[b,o,k] = sum_c W[o,c] * x[b,c,k] + bias[o]
// Grid (13 k-tiles, 4 o-groups, 8 b) = 416 blocks; each block stages all 64
// input channels for its k-tile and computes 16 output channels.
// ---------------------------------------------------------------------------
__global__ void k3b_linear(const float* __restrict__ W,
                           const float* __restrict__ bias,
                           float* __restrict__ out) {
    __shared__ float xs[CC][KT + 1];
    const int b  = blockIdx.z;
    const int og = blockIdx.y;                // 0..3
    const int k0 = blockIdx.x * KT;
    const int x  = threadIdx.x;
    const int y  = threadIdx.y;
    const int k  = k0 + x;
    const bool valid = (k < NN);
    const int kc = valid ? k : (NN - 1);

    for (int c = y; c < CC; c += 8)
        xs[c][x] = g_x[((size_t)b * CC + c) * NN + kc];
    __syncthreads();

    #pragma unroll
    for (int oi = 0; oi < 2; ++oi) {
        int o = og * 16 + y + oi * 8;
        float acc = bias[o];
        const float* wr = W + o * CC;
        #pragma unroll 16
        for (int c = 0; c < CC; ++c)
            acc = fmaf(wr[c], xs[c][x], acc);
        if (valid)
            out[((size_t)b * CC + o) * NN + k] = acc;
    }
}

// ---------------------------------------------------------------------------
extern "C" void kernel_launch(void* const* d_in, const int* in_sizes, int n_in,
                              void* d_out, int out_size) {
    const float* R    = (const float*)d_in[0];
    const float* W    = (const float*)d_in[1];
    const float* bias = (const float*)d_in[2];
    float*       out  = (float*)d_out;

    // Kernel 1: 1250 blocks x 256 (proven 80.6% DRAM SOL)
    {
        int total = BB * (NN2 / 4);
        k1_maxtanh<<<(total + 255) / 256, 256>>>(R);
    }

    // Transpose A -> At
    {
        dim3 grid((NN + 31) / 32, (NN + 31) / 32, BB);
        dim3 blk(32, 8);
        kT_transpose<<<grid, blk>>>();
    }

    // Kernel 2: 2048 blocks
    {
        dim3 grid((NV4 + 31) / 32, 8, BB * NS);
        dim3 blk(32, 8);
        k2_gather<<<grid, blk>>>(R);
    }

    // Kernel 3a: partial reduce (200 blocks)
    {
        int total4 = BB * CC * NV4;
        k3a_reduce<<<(total4 + 255) / 256, 256>>>();
    }

    // Kernel 3b: linear (416 blocks)
    {
        dim3 grid((NN + KT - 1) / KT, 4, BB);
        dim3 blk(32, 8);
        k3b_linear<<<grid, blk>>>(W, bias, out);
    }
}